// round 7
// baseline (speedup 1.0000x reference)
#include <cuda_runtime.h>

// x: (B=16, C=512, H=62, W=62) fp32, row-major.
// 9 regions: 2x2 patches at (y,x), y,x in {0,30,60}. flat base = y*62 + x.
// Patch elements: base, base+1, base+62, base+63. Pairs: (2k, 2k+1).
#define HW      3844
#define WIDTH   62
#define CHN     512
#define NPAIR   8
#define NREG    9
#define NCHUNK  16
#define NBLK    (NCHUNK * NPAIR)   // 128
#define NCELL   (NPAIR * NREG)     // 72
#define EPSV    1e-6f

__constant__ int c_posbase[9] = {0, 30, 60, 1860, 1890, 1920, 3720, 3750, 3780};
// region -> 5 negative region indices (region 8 = {2,4,5,6,7}; verified vs ref)
__constant__ int c_negidx[9][5] = {
    {1,3,4,2,6},
    {0,2,3,4,5},
    {0,1,4,5,8},
    {0,1,4,6,7},
    {0,1,3,5,7},
    {1,2,4,7,8},
    {0,3,4,7,8},
    {3,4,5,6,8},
    {2,4,5,6,7}
};

// Partials, chunk-contiguous for vectorized fold: [comp][pair][region][chunk].
// Fully overwritten each launch.
__device__ float        g_partial[3][NPAIR][NREG][NCHUNK];
__device__ unsigned int g_count;   // zero-init; last block resets each launch

struct Patch { float a, b, c, d, ss; };

__device__ __forceinline__ Patch load_patch(const float* __restrict__ plane, int base) {
    // base always even -> 8-byte aligned float2 loads
    float2 v01 = *reinterpret_cast<const float2*>(plane + base);
    float2 v23 = *reinterpret_cast<const float2*>(plane + base + WIDTH);
    Patch p;
    p.a = v01.x; p.b = v01.y; p.c = v23.x; p.d = v23.y;
    p.ss = fmaf(p.a, p.a, fmaf(p.b, p.b, fmaf(p.c, p.c, p.d * p.d)));
    return p;
}

// exp(cos(p,q)/TEMP) with clamp cos = dot / max(na*nb, EPS); TEMP = 0.1
__device__ __forceinline__ float cexp(const Patch& p, const Patch& q) {
    float dot = fmaf(p.a, q.a, fmaf(p.b, q.b, fmaf(p.c, q.c, p.d * q.d)));
    float d2  = p.ss * q.ss;                  // (na*nb)^2
    float inv = rsqrtf(d2);
    float cosv = (d2 >= EPSV * EPSV) ? dot * inv : dot * (1.0f / EPSV);
    return __expf(cosv * 10.0f);
}

__device__ __forceinline__ float sum16(const float* __restrict__ base) {
    // 16 contiguous floats = 4x float4, L2 hits, via ldcg (bypass possibly-stale L1)
    float4 v0 = __ldcg(reinterpret_cast<const float4*>(base) + 0);
    float4 v1 = __ldcg(reinterpret_cast<const float4*>(base) + 1);
    float4 v2 = __ldcg(reinterpret_cast<const float4*>(base) + 2);
    float4 v3 = __ldcg(reinterpret_cast<const float4*>(base) + 3);
    return ((v0.x + v0.y) + (v0.z + v0.w)) + ((v1.x + v1.y) + (v1.z + v1.w))
         + ((v2.x + v2.y) + (v2.z + v2.w)) + ((v3.x + v3.y) + (v3.z + v3.w));
}

__global__ __launch_bounds__(NREG * 32)
void lcl_fused(const float* __restrict__ x, float* __restrict__ out) {
    const int pair  = blockIdx.y;             // 0..7
    const int chunk = blockIdx.x;             // 0..15
    const int tid   = threadIdx.x;
    const int r     = tid >> 5;               // region = warp id, 0..8
    const int lane  = tid & 31;
    const int c     = chunk * 32 + lane;      // channel 0..511

    __shared__ Patch shp[2][NREG][32];        // stride-5 words: conflict-free
    __shared__ int   s_isLast;

    const float* p1 = x + ((size_t)(2 * pair) * CHN + (size_t)c) * HW;  // batch 2k
    const float* p2 = p1 + (size_t)CHN * HW;                            // batch 2k+1
    const int pb = c_posbase[r];
    Patch a1 = load_patch(p1, pb);            // own region only: 4 LDG.64/thread
    Patch a2 = load_patch(p2, pb);
    shp[0][r][lane] = a1;
    shp[1][r][lane] = a2;
    __syncthreads();

    float S  = cexp(a1, a2);
    float D1 = 0.0f, D2 = 0.0f;

#pragma unroll
    for (int n = 0; n < 5; n++) {
        const int j = c_negidx[r][n];
        const Patch b1 = shp[0][j][lane];     // i1n patch
        const Patch b2 = shp[1][j][lane];     // i2n patch
        D1 += cexp(a1, b1) + cexp(a1, b2);
        D2 += cexp(a2, b2) + cexp(a2, b1);
    }

#pragma unroll
    for (int o = 16; o; o >>= 1) {
        S  += __shfl_xor_sync(0xffffffffu, S,  o);
        D1 += __shfl_xor_sync(0xffffffffu, D1, o);
        D2 += __shfl_xor_sync(0xffffffffu, D2, o);
    }
    if (lane == 0) {
        g_partial[0][pair][r][chunk] = S;
        g_partial[1][pair][r][chunk] = D1;
        g_partial[2][pair][r][chunk] = D2;
        __threadfence();                      // release partials before ticket
    }
    __syncthreads();                          // all 27 partials of this block stored

    if (tid == 0)
        s_isLast = (atomicAdd(&g_count, 1u) == NBLK - 1u);
    __syncthreads();

    if (s_isLast && tid < 32) {               // warp 0 alone folds all 72 cells
        __threadfence();                      // acquire side of the ticket
        float acc = 0.0f;
#pragma unroll
        for (int cell = lane; cell < NCELL; cell += 32) {
            const int p  = cell / NREG;
            const int rr = cell - p * NREG;
            float Sx = sum16(&g_partial[0][p][rr][0]);
            float d1 = sum16(&g_partial[1][p][rr][0]);
            float d2 = sum16(&g_partial[2][p][rr][0]);
            // log((S+D1)/S) + log((S+D2)/S) = log( ((S+D1)/S) * ((S+D2)/S) )
            acc += logf(((Sx + d1) / Sx) * ((Sx + d2) / Sx));
        }
#pragma unroll
        for (int o = 16; o; o >>= 1)
            acc += __shfl_xor_sync(0xffffffffu, acc, o);
        if (lane == 0) {
            out[0] = acc * (1.0f / 144.0f);   // / BATCH(16) / N_REGIONS(9)
            g_count = 0;                      // reset for next graph replay
        }
    }
}

extern "C" void kernel_launch(void* const* d_in, const int* in_sizes, int n_in,
                              void* d_out, int out_size) {
    const float* x = (const float*)d_in[0];
    float* out = (float*)d_out;
    (void)in_sizes; (void)n_in; (void)out_size;

    dim3 grid(NCHUNK, NPAIR, 1);              // 128 blocks, one wave
    dim3 block(NREG * 32, 1, 1);              // 288 threads = 9 warps (1 per region)
    lcl_fused<<<grid, block>>>(x, out);
}

// round 9
// speedup vs baseline: 1.0669x; 1.0669x over previous
#include <cuda_runtime.h>

// x: (B=16, C=512, H=62, W=62) fp32, row-major.
// 9 regions: 2x2 patches at (y,x), y,x in {0,30,60}. flat base = y*62 + x.
// Patch elements: base, base+1, base+62, base+63. Pairs: (2k, 2k+1).
#define HW      3844
#define WIDTH   62
#define CHN     512
#define NPAIR   8
#define NREG    9
#define NCHUNK  16
#define NBLK    (NCHUNK * NPAIR)   // 128
#define NCELL   (NPAIR * NREG)     // 72
#define EPSV    1e-6f

__constant__ int c_posbase[9] = {0, 30, 60, 1860, 1890, 1920, 3720, 3750, 3780};
// region -> 5 negative region indices (region 8 = {2,4,5,6,7}; verified vs ref)
__constant__ int c_negidx[9][5] = {
    {1,3,4,2,6},
    {0,2,3,4,5},
    {0,1,4,5,8},
    {0,1,4,6,7},
    {0,1,3,5,7},
    {1,2,4,7,8},
    {0,3,4,7,8},
    {3,4,5,6,8},
    {2,4,5,6,7}
};

// Partials: [pair][chunk][region][{S,D1,D2}] — lane-0 writes 3 adjacent floats.
// Fully overwritten each launch.
__device__ float        g_partial[NPAIR][NCHUNK][NREG][3];
__device__ unsigned int g_count;   // zero-init; last block resets each launch

struct Patch { float a, b, c, d, ss; };

__device__ __forceinline__ Patch load_patch(const float* __restrict__ plane, int base) {
    // base always even -> 8-byte aligned float2 loads
    float2 v01 = *reinterpret_cast<const float2*>(plane + base);
    float2 v23 = *reinterpret_cast<const float2*>(plane + base + WIDTH);
    Patch p;
    p.a = v01.x; p.b = v01.y; p.c = v23.x; p.d = v23.y;
    p.ss = fmaf(p.a, p.a, fmaf(p.b, p.b, fmaf(p.c, p.c, p.d * p.d)));
    return p;
}

// exp(cos(p,q)/TEMP) with clamp cos = dot / max(na*nb, EPS); TEMP = 0.1
__device__ __forceinline__ float cexp(const Patch& p, const Patch& q) {
    float dot = fmaf(p.a, q.a, fmaf(p.b, q.b, fmaf(p.c, q.c, p.d * q.d)));
    float d2  = p.ss * q.ss;                  // (na*nb)^2
    float inv = rsqrtf(d2);
    float cosv = (d2 >= EPSV * EPSV) ? dot * inv : dot * (1.0f / EPSV);
    return __expf(cosv * 10.0f);
}

__global__ __launch_bounds__(NREG * 32)
void lcl_fused(const float* __restrict__ x, float* __restrict__ out) {
    const int pair  = blockIdx.y;             // 0..7
    const int chunk = blockIdx.x;             // 0..15
    const int tid   = threadIdx.x;
    const int r     = tid >> 5;               // region = warp id, 0..8
    const int lane  = tid & 31;
    const int c     = chunk * 32 + lane;      // channel 0..511

    __shared__ Patch shp[2][NREG][32];        // stride-5 words: conflict-free
    __shared__ float shv[NCELL];
    __shared__ int   s_isLast;

    const float* p1 = x + ((size_t)(2 * pair) * CHN + (size_t)c) * HW;  // batch 2k
    const float* p2 = p1 + (size_t)CHN * HW;                            // batch 2k+1
    const int pb = c_posbase[r];
    Patch a1 = load_patch(p1, pb);            // own region only: 4 LDG.64/thread
    Patch a2 = load_patch(p2, pb);
    shp[0][r][lane] = a1;
    shp[1][r][lane] = a2;
    __syncthreads();

    float S  = cexp(a1, a2);
    float D1 = 0.0f, D2 = 0.0f;

#pragma unroll
    for (int n = 0; n < 5; n++) {
        const int j = c_negidx[r][n];
        const Patch b1 = shp[0][j][lane];     // i1n patch
        const Patch b2 = shp[1][j][lane];     // i2n patch
        D1 += cexp(a1, b1) + cexp(a1, b2);
        D2 += cexp(a2, b2) + cexp(a2, b1);
    }

#pragma unroll
    for (int o = 16; o; o >>= 1) {
        S  += __shfl_xor_sync(0xffffffffu, S,  o);   // full warp active here
        D1 += __shfl_xor_sync(0xffffffffu, D1, o);
        D2 += __shfl_xor_sync(0xffffffffu, D2, o);
    }
    if (lane == 0) {
        g_partial[pair][chunk][r][0] = S;     // 3 adjacent floats: 1 sector
        g_partial[pair][chunk][r][1] = D1;
        g_partial[pair][chunk][r][2] = D2;
        __threadfence();                      // release partials before ticket
    }
    __syncthreads();

    if (tid == 0)
        s_isLast = (atomicAdd(&g_count, 1u) == NBLK - 1u);
    __syncthreads();

    if (s_isLast) {
        __threadfence();                      // acquire (block-uniform, no divergence)
        if (tid < NCELL) {                    // 72 cells; NO sync primitives inside
            const int p  = tid / NREG;
            const int rr = tid % NREG;
            float Sx = 0.0f, d1 = 0.0f, d2 = 0.0f;
#pragma unroll
            for (int ch = 0; ch < NCHUNK; ch++) {
                Sx += __ldcg(&g_partial[p][ch][rr][0]);
                d1 += __ldcg(&g_partial[p][ch][rr][1]);
                d2 += __ldcg(&g_partial[p][ch][rr][2]);
            }
            // log((S+D1)/S) + log((S+D2)/S), fused into one logf (range-safe)
            shv[tid] = logf(((Sx + d1) / Sx) * ((Sx + d2) / Sx));
        }
        __syncthreads();                      // block-uniform
        if (tid == 0) {
            float tot = 0.0f;
#pragma unroll
            for (int i = 0; i < NCELL; i++) tot += shv[i];
            out[0] = tot * (1.0f / 144.0f);   // / BATCH(16) / N_REGIONS(9)
            g_count = 0;                      // reset for next graph replay
        }
    }
}

extern "C" void kernel_launch(void* const* d_in, const int* in_sizes, int n_in,
                              void* d_out, int out_size) {
    const float* x = (const float*)d_in[0];
    float* out = (float*)d_out;
    (void)in_sizes; (void)n_in; (void)out_size;

    dim3 grid(NCHUNK, NPAIR, 1);              // 128 blocks, one wave
    dim3 block(NREG * 32, 1, 1);              // 288 threads = 9 warps (1 per region)
    lcl_fused<<<grid, block>>>(x, out);
}

// round 10
// speedup vs baseline: 1.0955x; 1.0269x over previous
#include <cuda_runtime.h>

// x: (B=16, C=512, H=62, W=62) fp32, row-major.
// 9 regions: 2x2 patches at (y,x), y,x in {0,30,60}. flat base = y*62 + x.
// Patch elements: base, base+1, base+62, base+63. Pairs: (2k, 2k+1).
#define HW      3844
#define WIDTH   62
#define CHN     512
#define NPAIR   8
#define NREG    9
#define NCHUNK  8                  // 8 chunks x 64 channels (2 per thread)
#define NBLK    (NCHUNK * NPAIR)   // 64 blocks
#define NCELL   (NPAIR * NREG)     // 72
#define EPSV    1e-6f

__constant__ int c_posbase[9] = {0, 30, 60, 1860, 1890, 1920, 3720, 3750, 3780};
// region -> 5 negative region indices (region 8 = {2,4,5,6,7}; verified vs ref)
__constant__ int c_negidx[9][5] = {
    {1,3,4,2,6},
    {0,2,3,4,5},
    {0,1,4,5,8},
    {0,1,4,6,7},
    {0,1,3,5,7},
    {1,2,4,7,8},
    {0,3,4,7,8},
    {3,4,5,6,8},
    {2,4,5,6,7}
};

// Partials: [pair][chunk][region][{S,D1,D2}] — lane-0 writes 3 adjacent floats.
// Fully overwritten each launch.
__device__ float        g_partial[NPAIR][NCHUNK][NREG][3];
__device__ unsigned int g_count;   // zero-init; last block resets each launch

struct Patch { float a, b, c, d, ss; };

__device__ __forceinline__ Patch load_patch(const float* __restrict__ plane, int base) {
    // base always even -> 8-byte aligned float2 loads
    float2 v01 = *reinterpret_cast<const float2*>(plane + base);
    float2 v23 = *reinterpret_cast<const float2*>(plane + base + WIDTH);
    Patch p;
    p.a = v01.x; p.b = v01.y; p.c = v23.x; p.d = v23.y;
    p.ss = fmaf(p.a, p.a, fmaf(p.b, p.b, fmaf(p.c, p.c, p.d * p.d)));
    return p;
}

// exp(cos(p,q)/TEMP) with clamp cos = dot / max(na*nb, EPS); TEMP = 0.1
__device__ __forceinline__ float cexp(const Patch& p, const Patch& q) {
    float dot = fmaf(p.a, q.a, fmaf(p.b, q.b, fmaf(p.c, q.c, p.d * q.d)));
    float d2  = p.ss * q.ss;                  // (na*nb)^2
    float inv = rsqrtf(d2);
    float cosv = (d2 >= EPSV * EPSV) ? dot * inv : dot * (1.0f / EPSV);
    return __expf(cosv * 10.0f);
}

__global__ __launch_bounds__(NREG * 32)
void lcl_fused(const float* __restrict__ x, float* __restrict__ out) {
    const int pair  = blockIdx.y;             // 0..7
    const int chunk = blockIdx.x;             // 0..7
    const int tid   = threadIdx.x;
    const int r     = tid >> 5;               // region = warp id, 0..8
    const int lane  = tid & 31;
    const int c0    = chunk * 64 + lane;      // this thread's two channels: c0, c0+32

    __shared__ Patch shp[2][2][NREG][32];     // [chan-half][plane][region][lane]
    __shared__ float shv[NCELL];
    __shared__ int   s_isLast;

    const int pb = c_posbase[r];
    const size_t planeStride = (size_t)HW;
    {
        const float* p1 = x + ((size_t)(2 * pair) * CHN + (size_t)c0) * HW;   // batch 2k
        const float* p2 = p1 + (size_t)CHN * HW;                              // batch 2k+1
        // 8 independent LDG.64 per thread (MLP=8)
        shp[0][0][r][lane] = load_patch(p1, pb);
        shp[0][1][r][lane] = load_patch(p2, pb);
        shp[1][0][r][lane] = load_patch(p1 + 32 * planeStride * CHN / CHN * 0 + (size_t)32 * HW, pb);
        shp[1][1][r][lane] = load_patch(p2 + (size_t)32 * HW, pb);
    }
    __syncthreads();

    float S = 0.0f, D1 = 0.0f, D2 = 0.0f;

#pragma unroll
    for (int h = 0; h < 2; h++) {             // two channel-halves
        const Patch a1 = shp[h][0][r][lane];
        const Patch a2 = shp[h][1][r][lane];
        S += cexp(a1, a2);
#pragma unroll
        for (int n = 0; n < 5; n++) {
            const int j = c_negidx[r][n];
            const Patch b1 = shp[h][0][j][lane];
            const Patch b2 = shp[h][1][j][lane];
            D1 += cexp(a1, b1) + cexp(a1, b2);
            D2 += cexp(a2, b2) + cexp(a2, b1);
        }
    }

#pragma unroll
    for (int o = 16; o; o >>= 1) {
        S  += __shfl_xor_sync(0xffffffffu, S,  o);   // full warp active
        D1 += __shfl_xor_sync(0xffffffffu, D1, o);
        D2 += __shfl_xor_sync(0xffffffffu, D2, o);
    }
    if (lane == 0) {
        g_partial[pair][chunk][r][0] = S;     // 3 adjacent floats: 1 sector
        g_partial[pair][chunk][r][1] = D1;
        g_partial[pair][chunk][r][2] = D2;
        __threadfence();                      // release partials before ticket
    }
    __syncthreads();

    if (tid == 0)
        s_isLast = (atomicAdd(&g_count, 1u) == NBLK - 1u);
    __syncthreads();

    if (s_isLast) {
        __threadfence();                      // acquire (block-uniform)
        if (tid < NCELL) {                    // 72 cells; no sync inside divergence
            const int p  = tid / NREG;
            const int rr = tid % NREG;
            float Sx = 0.0f, d1 = 0.0f, d2 = 0.0f;
#pragma unroll
            for (int ch = 0; ch < NCHUNK; ch++) {
                Sx += __ldcg(&g_partial[p][ch][rr][0]);
                d1 += __ldcg(&g_partial[p][ch][rr][1]);
                d2 += __ldcg(&g_partial[p][ch][rr][2]);
            }
            // log((S+D1)/S) + log((S+D2)/S), fused into one logf (range-safe)
            shv[tid] = logf(((Sx + d1) / Sx) * ((Sx + d2) / Sx));
        }
        __syncthreads();                      // block-uniform
        if (tid == 0) {
            float tot = 0.0f;
#pragma unroll
            for (int i = 0; i < NCELL; i++) tot += shv[i];
            out[0] = tot * (1.0f / 144.0f);   // / BATCH(16) / N_REGIONS(9)
            g_count = 0;                      // reset for next graph replay
        }
    }
}

extern "C" void kernel_launch(void* const* d_in, const int* in_sizes, int n_in,
                              void* d_out, int out_size) {
    const float* x = (const float*)d_in[0];
    float* out = (float*)d_out;
    (void)in_sizes; (void)n_in; (void)out_size;

    dim3 grid(NCHUNK, NPAIR, 1);              // 64 blocks
    dim3 block(NREG * 32, 1, 1);              // 288 threads = 9 warps (1 per region)
    lcl_fused<<<grid, block>>>(x, out);
}

// round 11
// speedup vs baseline: 1.1398x; 1.0404x over previous
#include <cuda_runtime.h>

// x: (B=16, C=512, H=62, W=62) fp32, row-major.
// 9 regions: 2x2 patches at (y,x), y,x in {0,30,60}. flat base = y*62 + x.
// Patch elements: base, base+1, base+62, base+63. Pairs: (2k, 2k+1).
#define HW      3844
#define WIDTH   62
#define CHN     512
#define NPAIR   8
#define NREG    9
#define NCHUNK  16
#define NBLK    (NCHUNK * NPAIR)   // 128
#define EPSV    1e-6f

__constant__ int c_posbase[9] = {0, 30, 60, 1860, 1890, 1920, 3720, 3750, 3780};
// region -> 5 negative region indices (region 8 = {2,4,5,6,7}; verified vs ref)
__constant__ int c_negidx[9][5] = {
    {1,3,4,2,6},
    {0,2,3,4,5},
    {0,1,4,5,8},
    {0,1,4,6,7},
    {0,1,3,5,7},
    {1,2,4,7,8},
    {0,3,4,7,8},
    {3,4,5,6,8},
    {2,4,5,6,7}
};

// Partials: [pair][chunk][region][{S,D1,D2}] — fully overwritten every launch.
__device__ float        g_partial[NPAIR][NCHUNK][NREG][3];
__device__ unsigned int g_count;   // zero-init; last block resets each launch

struct Patch { float a, b, c, d, ss; };

__device__ __forceinline__ Patch load_patch(const float* __restrict__ plane, int base) {
    // base always even -> 8-byte aligned float2 loads
    float2 v01 = *reinterpret_cast<const float2*>(plane + base);
    float2 v23 = *reinterpret_cast<const float2*>(plane + base + WIDTH);
    Patch p;
    p.a = v01.x; p.b = v01.y; p.c = v23.x; p.d = v23.y;
    p.ss = fmaf(p.a, p.a, fmaf(p.b, p.b, fmaf(p.c, p.c, p.d * p.d)));
    return p;
}

// exp(cos(p,q)/TEMP) with clamp cos = dot / max(na*nb, EPS); TEMP = 0.1
__device__ __forceinline__ float cexp(const Patch& p, const Patch& q) {
    float dot = fmaf(p.a, q.a, fmaf(p.b, q.b, fmaf(p.c, q.c, p.d * q.d)));
    float d2  = p.ss * q.ss;                  // (na*nb)^2
    float inv = rsqrtf(d2);
    float cosv = (d2 >= EPSV * EPSV) ? dot * inv : dot * (1.0f / EPSV);
    return __expf(cosv * 10.0f);
}

__global__ __launch_bounds__(NREG * 32)
void lcl_fused(const float* __restrict__ x, float* __restrict__ out) {
    const int pair  = blockIdx.y;             // 0..7
    const int chunk = blockIdx.x;             // 0..15
    const int tid   = threadIdx.x;
    const int r     = tid >> 5;               // region = warp id, 0..8
    const int lane  = tid & 31;
    const int c     = chunk * 32 + lane;      // channel 0..511

    // Stage patches in smem: [plane][region][lane]; stride 5 words -> conflict-free
    __shared__ Patch shp[2][NREG][32];
    __shared__ float shv[NPAIR * NREG];
    __shared__ int   s_isLast;

    {
        const float* p1 = x + ((size_t)(2 * pair) * CHN + (size_t)c) * HW;  // batch 2k
        const float* p2 = p1 + (size_t)CHN * HW;                            // batch 2k+1
        const int pb = c_posbase[r];
        shp[0][r][lane] = load_patch(p1, pb);   // each warp loads only its region
        shp[1][r][lane] = load_patch(p2, pb);
    }
    __syncthreads();

    const Patch a1 = shp[0][r][lane];
    const Patch a2 = shp[1][r][lane];

    float S  = cexp(a1, a2);
    float D1 = 0.0f, D2 = 0.0f;

#pragma unroll
    for (int n = 0; n < 5; n++) {
        const int j = c_negidx[r][n];
        const Patch b1 = shp[0][j][lane];     // i1n patch
        const Patch b2 = shp[1][j][lane];     // i2n patch
        D1 += cexp(a1, b1) + cexp(a1, b2);
        D2 += cexp(a2, b2) + cexp(a2, b1);
    }

#pragma unroll
    for (int o = 16; o; o >>= 1) {
        S  += __shfl_xor_sync(0xffffffffu, S,  o);
        D1 += __shfl_xor_sync(0xffffffffu, D1, o);
        D2 += __shfl_xor_sync(0xffffffffu, D2, o);
    }
    if (lane == 0) {
        g_partial[pair][chunk][r][0] = S;
        g_partial[pair][chunk][r][1] = D1;
        g_partial[pair][chunk][r][2] = D2;
        __threadfence();                      // make this warp's partials visible
    }
    __syncthreads();

    if (tid == 0)
        s_isLast = (atomicAdd(&g_count, 1u) == NBLK - 1u);
    __syncthreads();

    if (s_isLast) {
        // Final fold: 72 (pair,region) cells, 16 chunk-partials each.
        if (tid < NPAIR * NREG) {
            const int p  = tid / NREG;
            const int rr = tid % NREG;
            float Sx = 0.0f, d1 = 0.0f, d2 = 0.0f;
#pragma unroll
            for (int ch = 0; ch < NCHUNK; ch++) {
                Sx += __ldcg(&g_partial[p][ch][rr][0]);
                d1 += __ldcg(&g_partial[p][ch][rr][1]);
                d2 += __ldcg(&g_partial[p][ch][rr][2]);
            }
            // -log(S/(S+D1)) - log(S/(S+D2))
            shv[tid] = logf((Sx + d1) / Sx) + logf((Sx + d2) / Sx);
        }
        __syncthreads();
        if (tid == 0) {
            float tot = 0.0f;
#pragma unroll
            for (int i = 0; i < NPAIR * NREG; i++) tot += shv[i];
            out[0] = tot * (1.0f / 144.0f);   // / BATCH(16) / N_REGIONS(9)
            g_count = 0;                      // reset for next graph replay
        }
    }
}

extern "C" void kernel_launch(void* const* d_in, const int* in_sizes, int n_in,
                              void* d_out, int out_size) {
    const float* x = (const float*)d_in[0];
    float* out = (float*)d_out;
    (void)in_sizes; (void)n_in; (void)out_size;

    dim3 grid(NCHUNK, NPAIR, 1);              // 128 blocks, one wave
    dim3 block(NREG * 32, 1, 1);              // 288 threads = 9 warps (1 per region)
    lcl_fused<<<grid, block>>>(x, out);
}